// round 10
// baseline (speedup 1.0000x reference)
#include <cuda_runtime.h>
#include <math.h>
#include <stdint.h>

// Problem constants (fixed shapes per reference)
#define DEPTH    8
#define NN       255        // internal nodes
#define NL       256        // leaves (K dim)
#define NCLS     200        // classes
#define BT       16         // batch tile per block
#define KS       5          // k-split factor (chunks 52,51,51,51,51)

// ---- smem layout (bytes) ----
// [0..16)    : two mbarriers
// [16..20496): s_ew  [256 leaves][stride 20 floats] = 20,480 B
// [20496..+204800): s_el [256 k][200 floats]
//     er/elp overlay (10,200 floats = 40,800 B) lives at the TAIL of s_el,
//     which is EXACTLY the region of EL rows 205..255.
//     Early TMA copy = rows 0..204 (164,000 B), issued at kernel start,
//     overlaps phases A+B. Late copy = rows 205..255 = exactly chunk ks==4.
// [..+1024)  : pad for harmless prefetch over-reads
#define MBAR_BYTES   16
#define EW_FLOATS    (NL * 20)                  // 5120
#define EL_FLOATS    (NL * NCLS)                // 51200
#define PAD_BYTES    1024
#define SMEM_BYTES   (MBAR_BYTES + (EW_FLOATS + EL_FLOATS) * 4 + PAD_BYTES)

#define EL_SPLIT_ROW 205
#define EL_EARLY_SZ  (EL_SPLIT_ROW * NCLS * 4)          // 164,000 B
#define EL_LATE_OFF  EL_EARLY_SZ
#define EL_LATE_SZ   ((NL - EL_SPLIT_ROW) * NCLS * 4)   // 40,800 B
#define OVL_OFF      (EL_SPLIT_ROW * NCLS)              // 41,000 floats

__device__ __align__(16) float g_EL[NL * NCLS];

typedef unsigned long long u64;

__device__ __forceinline__ u64 pk2(float lo, float hi) {
    u64 r;
    asm("mov.b64 %0, {%1, %2};" : "=l"(r) : "f"(lo), "f"(hi));
    return r;
}
__device__ __forceinline__ u64 fma2(u64 a, u64 b, u64 c) {
    u64 d;
    asm("fma.rn.f32x2 %0, %1, %2, %3;" : "=l"(d) : "l"(a), "l"(b), "l"(c));
    return d;
}
__device__ __forceinline__ void upk2(u64 v, float& lo, float& hi) {
    asm("mov.b64 {%0, %1}, %2;" : "=f"(lo), "=f"(hi) : "l"(v));
}

__device__ __forceinline__ uint32_t smem_u32(const void* p) {
    uint32_t a;
    asm("{ .reg .u64 t; cvta.to.shared.u64 t, %1; cvt.u32.u64 %0, t; }"
        : "=r"(a) : "l"(p));
    return a;
}
__device__ __forceinline__ void mbar_init(uint32_t mbar, uint32_t cnt) {
    asm volatile("mbarrier.init.shared.b64 [%0], %1;" :: "r"(mbar), "r"(cnt) : "memory");
}
__device__ __forceinline__ void mbar_expect_tx(uint32_t mbar, uint32_t bytes) {
    asm volatile("mbarrier.arrive.expect_tx.shared.b64 _, [%0], %1;"
                 :: "r"(mbar), "r"(bytes) : "memory");
}
__device__ __forceinline__ void bulk_copy_g2s(uint32_t dst, const void* src,
                                              uint32_t bytes, uint32_t mbar) {
    asm volatile(
        "cp.async.bulk.shared::cluster.global.mbarrier::complete_tx::bytes "
        "[%0], [%1], %2, [%3];"
        :: "r"(dst), "l"(src), "r"(bytes), "r"(mbar) : "memory");
}
__device__ __forceinline__ void mbar_wait(uint32_t mbar, uint32_t parity) {
    uint32_t done;
    asm volatile(
        "{\n\t.reg .pred p;\n\t"
        "mbarrier.try_wait.parity.acquire.cta.shared::cta.b64 p, [%1], %2;\n\t"
        "selp.b32 %0, 1, 0, p;\n\t}"
        : "=r"(done) : "r"(mbar), "r"(parity) : "memory");
    if (!done) {
        asm volatile(
            "{\n\t.reg .pred P1;\n\t"
            "W%=:\n\t"
            "mbarrier.try_wait.parity.acquire.cta.shared::cta.b64 P1, [%0], %1, 0x989680;\n\t"
            "@P1 bra.uni D%=;\n\t"
            "bra.uni W%=;\n\t"
            "D%=:\n\t}"
            :: "r"(mbar), "r"(parity) : "memory");
    }
}

// ---------------- kernel 1: row softmax of leaf_logits ----------------
__global__ void leaf_softmax_kernel(const float* __restrict__ logits) {
    const int wid  = threadIdx.x >> 5;
    const int lane = threadIdx.x & 31;
    const int leaf = blockIdx.x * 8 + wid;
    const float* row = logits + leaf * NCLS;

    float v[7];
    float m = -INFINITY;
#pragma unroll
    for (int i = 0; i < 7; i++) {
        int c = lane + 32 * i;
        v[i] = (c < NCLS) ? row[c] : -INFINITY;
        m = fmaxf(m, v[i]);
    }
#pragma unroll
    for (int o = 16; o; o >>= 1) m = fmaxf(m, __shfl_xor_sync(0xffffffffu, m, o));

    float s = 0.f;
#pragma unroll
    for (int i = 0; i < 7; i++) {
        v[i] = expf(v[i] - m);
        s += v[i];
    }
#pragma unroll
    for (int o = 16; o; o >>= 1) s += __shfl_xor_sync(0xffffffffu, s, o);

    const float r = 1.0f / s;
#pragma unroll
    for (int i = 0; i < 7; i++) {
        int c = lane + 32 * i;
        if (c < NCLS) g_EL[leaf * NCLS + c] = v[i] * r;
    }
}

// Software-pipelined GEMM inner loop: n iterations, prefetch depth 1.
// ew steps by 5 float4 per k, el steps by 50 float4 per k. The final
// prefetch over-reads one iteration past the range (lands in pad/adjacent
// smem; values never consumed).
__device__ __forceinline__ void gemm_run(const float4* __restrict__ ew,
                                         const float4* __restrict__ el,
                                         int n, u64 (&acc)[4][2]) {
    float4 w = ew[0];
    float4 e = el[0];
#pragma unroll 4
    for (int i = 0; i < n; i++) {
        const float4 wn = ew[(i + 1) * 5];    // prefetch next iteration
        const float4 en = el[(i + 1) * 50];
        const u64 e01 = pk2(e.x, e.y);
        const u64 e23 = pk2(e.z, e.w);
        u64 wd;
        wd = pk2(w.x, w.x);
        acc[0][0] = fma2(wd, e01, acc[0][0]);
        acc[0][1] = fma2(wd, e23, acc[0][1]);
        wd = pk2(w.y, w.y);
        acc[1][0] = fma2(wd, e01, acc[1][0]);
        acc[1][1] = fma2(wd, e23, acc[1][1]);
        wd = pk2(w.z, w.z);
        acc[2][0] = fma2(wd, e01, acc[2][0]);
        acc[2][1] = fma2(wd, e23, acc[2][1]);
        wd = pk2(w.w, w.w);
        acc[3][0] = fma2(wd, e01, acc[3][0]);
        acc[3][1] = fma2(wd, e23, acc[3][1]);
        w = wn;
        e = en;
    }
}

// ---------------- kernel 2: fused tree-walk + GEMM + log ----------------
// grid = 128 (B/16), 1024 threads. KS=5 -> 1000 active mainloop threads.
__global__ __launch_bounds__(1024, 1)
void tree_gemm_kernel(const float* __restrict__ sims, float* __restrict__ out,
                      const int B) {
    extern __shared__ __align__(16) char smraw[];
    const uint32_t mbarA = smem_u32(smraw);        // early EL copy (rows 0..204)
    const uint32_t mbarB = smem_u32(smraw) + 8;    // late EL copy (rows 205..255)
    float* s_ew = (float*)(smraw + MBAR_BYTES);    // [leaf][20]
    float* s_el = s_ew + EW_FLOATS;                // [k][200]
    float* s_er  = s_el + OVL_OFF;                 // [node][20] overlay (tail)
    float* s_elp = s_el + OVL_OFF + NN * 20;       // [node][20] overlay (tail)

    const int tid = threadIdx.x;
    const int b0  = blockIdx.x * BT;

    // ---- init mbarriers + issue EARLY TMA copy (EL rows 0..204) ----
    if (tid == 0) {
        mbar_init(mbarA, 1);
        mbar_init(mbarB, 1);
        asm volatile("fence.proxy.async.shared::cta;" ::: "memory");
        mbar_expect_tx(mbarA, EL_EARLY_SZ);
        bulk_copy_g2s(smem_u32(s_el), g_EL, EL_EARLY_SZ, mbarA);
    }

    // ---- Phase A: sims tile -> routing probabilities (tail of s_el) ----
    for (int i = tid; i < NN * BT; i += 1024) {
        const int n = i >> 4;
        const int b = i & 15;
        float s = 0.0f;
        if (b0 + b < B) s = sims[n * B + b0 + b];
        const float a = fabsf(s) + 1e-7f;
        s_er[n * 20 + b]  = expf(s);       // P(right)
        s_elp[n * 20 + b] = -expm1f(-a);   // P(left) = 1 - exp(-(|s|+eps))
    }
    __syncthreads();

    // ---- Phase B: per-leaf path products -> EW[leaf][b] ----
    {
        const int leaf = tid >> 2;          // 0..255
        const int bq   = tid & 3;           // batch quad 0..3
        float4 w = make_float4(1.f, 1.f, 1.f, 1.f);
        int node = 0;
#pragma unroll
        for (int lvl = 0; lvl < DEPTH; lvl++) {
            const int bit = (leaf >> (7 - lvl)) & 1;
            const float* base = bit ? s_er : s_elp;
            const float4 f = *(const float4*)(base + node * 20 + bq * 4);
            w.x *= f.x; w.y *= f.y; w.z *= f.z; w.w *= f.w;
            node = 2 * node + 1 + bit;
        }
        *(float4*)(s_ew + leaf * 20 + bq * 4) = w;
    }
    __syncthreads();   // overlay reads done -> tail of s_el reusable

    // ---- issue LATE TMA copy (EL rows 205..255 over the overlay) ----
    if (tid == 0) {
        mbar_expect_tx(mbarB, EL_LATE_SZ);
        bulk_copy_g2s(smem_u32((char*)s_el + EL_LATE_OFF),
                      (const char*)g_EL + EL_LATE_OFF, EL_LATE_SZ, mbarB);
    }
    mbar_wait(mbarA, 0);   // rows 0..204 ready: everything ks<=3 needs

    // ---- Phase C: k-split GEMM (KS=5, chunks 52,51,51,51,51) ----
    const int ks = tid / 200;            // 0..4 active, 5 = idle (tid>=1000)
    const int r  = tid - ks * 200;       // 0..199
    const int bg = r & 3;                // batch quad
    const int cg = r >> 2;               // class quad 0..49
    const bool active = (tid < 1000);

    u64 acc[4][2];
#pragma unroll
    for (int i = 0; i < 4; i++) { acc[i][0] = 0ull; acc[i][1] = 0ull; }

    if (active) {
        const int kbase = ks * 51 + (ks > 0 ? 1 : 0);   // 0,52,103,154,205
        const float4* ew = (const float4*)s_ew + kbase * 5 + bg;
        const float4* el = (const float4*)s_el + kbase * 50 + cg;
        if (ks == 0) {
            gemm_run(ew, el, 52, acc);
        } else if (ks < 4) {
            gemm_run(ew, el, 51, acc);
        } else {
            mbar_wait(mbarB, 0);          // only ks==4 touches rows 205..255
            gemm_run(ew, el, 51, acc);
        }
    }

    // ---- combine k-split partials through smem (reuse s_el front) ----
    __syncthreads();
    float* part = s_el;   // 4 groups * 200 threads * 16 floats = 12,800 floats
    if (active && ks > 0) {
        float* p = part + (((ks - 1) * 200) + r) * 16;
        float x[16];
        upk2(acc[0][0], x[0],  x[1]);  upk2(acc[0][1], x[2],  x[3]);
        upk2(acc[1][0], x[4],  x[5]);  upk2(acc[1][1], x[6],  x[7]);
        upk2(acc[2][0], x[8],  x[9]);  upk2(acc[2][1], x[10], x[11]);
        upk2(acc[3][0], x[12], x[13]); upk2(acc[3][1], x[14], x[15]);
        ((float4*)p)[0] = make_float4(x[0],  x[1],  x[2],  x[3]);
        ((float4*)p)[1] = make_float4(x[4],  x[5],  x[6],  x[7]);
        ((float4*)p)[2] = make_float4(x[8],  x[9],  x[10], x[11]);
        ((float4*)p)[3] = make_float4(x[12], x[13], x[14], x[15]);
    }
    __syncthreads();

    // ---- Epilogue: ks==0 threads reduce + __logf + coalesced store ----
    if (active && ks == 0) {
        float x[16];
        upk2(acc[0][0], x[0],  x[1]);  upk2(acc[0][1], x[2],  x[3]);
        upk2(acc[1][0], x[4],  x[5]);  upk2(acc[1][1], x[6],  x[7]);
        upk2(acc[2][0], x[8],  x[9]);  upk2(acc[2][1], x[10], x[11]);
        upk2(acc[3][0], x[12], x[13]); upk2(acc[3][1], x[14], x[15]);
#pragma unroll
        for (int s = 1; s < KS; s++) {
            const float4* p =
                (const float4*)(part + (((s - 1) * 200) + r) * 16);
            const float4 a0 = p[0], a1 = p[1], a2 = p[2], a3 = p[3];
            x[0]  += a0.x; x[1]  += a0.y; x[2]  += a0.z; x[3]  += a0.w;
            x[4]  += a1.x; x[5]  += a1.y; x[6]  += a1.z; x[7]  += a1.w;
            x[8]  += a2.x; x[9]  += a2.y; x[10] += a2.z; x[11] += a2.w;
            x[12] += a3.x; x[13] += a3.y; x[14] += a3.z; x[15] += a3.w;
        }
        const int c0 = cg * 4;
#pragma unroll
        for (int i = 0; i < 4; i++) {
            const int b = b0 + bg * 4 + i;
            if (b < B) {
                float4 o;
                o.x = __logf(x[i * 4 + 0]);
                o.y = __logf(x[i * 4 + 1]);
                o.z = __logf(x[i * 4 + 2]);
                o.w = __logf(x[i * 4 + 3]);
                *((float4*)(out + (size_t)b * NCLS + c0)) = o;
            }
        }
    }
}

extern "C" void kernel_launch(void* const* d_in, const int* in_sizes, int n_in,
                              void* d_out, int out_size) {
    const float* sims   = (const float*)d_in[0];
    const float* logits = (const float*)d_in[1];
    int sims_sz = in_sizes[0];
    if (n_in >= 2 && in_sizes[0] == NL * NCLS) {   // defensive input-order check
        const float* tmp = sims; sims = logits; logits = tmp;
        sims_sz = in_sizes[1];
    }
    const int B = sims_sz / NN;   // 2048

    cudaFuncSetAttribute(tree_gemm_kernel,
                         cudaFuncAttributeMaxDynamicSharedMemorySize, SMEM_BYTES);

    leaf_softmax_kernel<<<NL / 8, 256>>>(logits);
    tree_gemm_kernel<<<(B + BT - 1) / BT, 1024, SMEM_BYTES>>>(sims, (float*)d_out, B);
}